// round 16
// baseline (speedup 1.0000x reference)
#include <cuda_runtime.h>
#include <cuda_bf16.h>
#include <math.h>
#include <stdint.h>

// Problem constants
#define T_LEN 512
#define B_SZ  64
#define I_SZ  512
#define H_SZ  1024
#define G3H   3072
#define M_TOT 32768          // T*B

#define NBLK  128            // persistent blocks (1 per SM)
#define JT    8              // hidden units per block
#define NROW  24             // gate rows per block

// ---- scan smem (bytes) ----
#define WROWB   2064                        // W row stride (1024*2 + 16 pad)
#define WPL     (24 * WROWB)                // 49536 per plane (hi / lo)
#define OFF_A   (2 * WPL)                   // 99072
#define AROW    80                          // A row: 32B hi + 32B lo + 16 pad
#define ATILE   (16 * AROW)                 // 1280 per buffer
#define WARPA   (2 * ATILE)                 // 2560 per warp (depth 2)
#define OFF_RED (OFF_A + 32 * WARPA)        // 99072 + 81920 = 180992
#define REDW    24
#define SMEM_SCAN (OFF_RED + 8 * 64 * REDW * 4)   // 230144

// ---- gemm smem (bytes) ----
#define GA_PLANE (128 * 48)           // 6144
#define GB_PLANE (64 * 48)            // 3072
#define GBUF     (2 * GA_PLANE + 2 * GB_PLANE)   // 18432
#define SMEM_GEMM (2 * GBUF)          // 36864

typedef unsigned long long ull;
typedef unsigned short u16;

__device__ __align__(16) float g_gates[(size_t)M_TOT * G3H];
__device__ __align__(16) float g_h0[B_SZ * H_SZ];           // zeros, never written
__device__ __align__(16) u16 g_hhi[B_SZ * H_SZ];            // h bf16 hi
__device__ __align__(16) u16 g_hlo[B_SZ * H_SZ];            // h bf16 lo
__device__ __align__(16) u16 g_xhi[(size_t)M_TOT * I_SZ];   // x bf16 hi
__device__ __align__(16) u16 g_xlo[(size_t)M_TOT * I_SZ];   // x bf16 lo
__device__ __align__(16) u16 g_whi[(size_t)G3H * I_SZ];     // w_ih bf16 hi
__device__ __align__(16) u16 g_wlo[(size_t)G3H * I_SZ];     // w_ih bf16 lo
__device__ unsigned g_sync;

// ---------------------------------------------------------------------------
// helpers
// ---------------------------------------------------------------------------
__device__ __forceinline__ void mma16816(float* d, const unsigned* a,
                                         const unsigned* b) {
    asm volatile(
        "mma.sync.aligned.m16n8k16.row.col.f32.bf16.bf16.f32 "
        "{%0,%1,%2,%3}, {%4,%5,%6,%7}, {%8,%9}, {%0,%1,%2,%3};"
        : "+f"(d[0]), "+f"(d[1]), "+f"(d[2]), "+f"(d[3])
        : "r"(a[0]), "r"(a[1]), "r"(a[2]), "r"(a[3]), "r"(b[0]), "r"(b[1]));
}
__device__ __forceinline__ void ldmat4(unsigned* r, uint32_t addr) {
    asm volatile("ldmatrix.sync.aligned.m8n8.x4.shared.b16 {%0,%1,%2,%3}, [%4];"
                 : "=r"(r[0]), "=r"(r[1]), "=r"(r[2]), "=r"(r[3]) : "r"(addr));
}
__device__ __forceinline__ unsigned pack_bf2(float a, float b) {
    __nv_bfloat16 x = __float2bfloat16_rn(a);
    __nv_bfloat16 y = __float2bfloat16_rn(b);
    return (unsigned)__bfloat16_as_ushort(x)
         | ((unsigned)__bfloat16_as_ushort(y) << 16);
}
#define CP16(dst, src) \
    asm volatile("cp.async.cg.shared.global [%0], [%1], 16;" \
                 :: "r"(dst), "l"(src) : "memory")
#define CP_COMMIT() asm volatile("cp.async.commit_group;" ::: "memory")
#define CP_WAIT(n)  asm volatile("cp.async.wait_group %0;" :: "n"(n) : "memory")

// ---------------------------------------------------------------------------
// Conversion: f32 -> bf16 hi/lo
// ---------------------------------------------------------------------------
__global__ void cvt_hilo(const float* __restrict__ src,
                         u16* __restrict__ hi, u16* __restrict__ lo, int n4)
{
    int i = blockIdx.x * 256 + threadIdx.x;
    if (i >= n4) return;
    float4 v = ((const float4*)src)[i];
    unsigned h0 = pack_bf2(v.x, v.y);
    unsigned h1 = pack_bf2(v.z, v.w);
    float rx = v.x - __bfloat162float(__ushort_as_bfloat16((u16)h0));
    float ry = v.y - __bfloat162float(__ushort_as_bfloat16((u16)(h0 >> 16)));
    float rz = v.z - __bfloat162float(__ushort_as_bfloat16((u16)h1));
    float rw = v.w - __bfloat162float(__ushort_as_bfloat16((u16)(h1 >> 16)));
    ((uint2*)hi)[i] = make_uint2(h0, h1);
    ((uint2*)lo)[i] = make_uint2(pack_bf2(rx, ry), pack_bf2(rz, rw));
}

// ---------------------------------------------------------------------------
// Kernel A: x_gates = x @ w_ih^T + b_ih via mma.sync bf16 hi/lo (3-pass).
// (unchanged — verified)
// ---------------------------------------------------------------------------
__global__ __launch_bounds__(256)
void gemm_xgates_mma(const float* __restrict__ bias)
{
    extern __shared__ __align__(16) char smem[];
    uint32_t sm32 = (uint32_t)__cvta_generic_to_shared((void*)smem);

    const int tid  = threadIdx.x;
    const int w    = tid >> 5;
    const int lane = tid & 31;
    const int wm   = w & 3;
    const int wn   = w >> 2;
    const int m0   = blockIdx.y * 128;
    const int n0   = blockIdx.x * 64;

    const int arow = tid >> 1, akh = tid & 1;
    const int bhl = tid >> 7, brem = tid & 127;
    const int brow = brem >> 1, bkh = brem & 1;

    float acc[2][4][4];
    #pragma unroll
    for (int mt = 0; mt < 2; mt++)
        #pragma unroll
        for (int nt = 0; nt < 4; nt++)
            #pragma unroll
            for (int i = 0; i < 4; i++) acc[mt][nt][i] = 0.f;

    auto stage = [&](int kt, int buf) {
        const int k0 = kt * 16;
        uint32_t bb = sm32 + (uint32_t)(buf * GBUF);
        uint32_t adst = bb + (uint32_t)(arow * 48 + akh * 16);
        const size_t asrc = (size_t)(m0 + arow) * I_SZ + k0 + akh * 8;
        CP16(adst,            g_xhi + asrc);
        CP16(adst + GA_PLANE, g_xlo + asrc);
        uint32_t bdst = bb + (uint32_t)(2 * GA_PLANE + bhl * GB_PLANE
                                        + brow * 48 + bkh * 16);
        const u16* bsrc = (bhl ? g_wlo : g_whi)
                        + (size_t)(n0 + brow) * I_SZ + k0 + bkh * 8;
        CP16(bdst, bsrc);
    };

    stage(0, 0);
    CP_COMMIT();

    const uint32_t lmA = (uint32_t)((wm * 32 + (lane & 15)) * 48
                                    + (lane >> 4) * 16);
    const int bnr = wn * 32 + (lane >> 2);
    const int bkl = (lane & 3) * 4;

    #pragma unroll 1
    for (int kt = 0; kt < 32; kt++) {
        const int buf = kt & 1;
        if (kt < 31) { stage(kt + 1, buf ^ 1); }
        CP_COMMIT();
        CP_WAIT(1);
        __syncthreads();

        uint32_t bb = sm32 + (uint32_t)(buf * GBUF);
        const char* bgen = smem + (size_t)buf * GBUF;

        unsigned Bh[4][2], Bl[4][2];
        #pragma unroll
        for (int nt = 0; nt < 4; nt++) {
            const char* p = bgen + 2 * GA_PLANE + (bnr + nt * 8) * 48 + bkl;
            Bh[nt][0] = *(const unsigned*)p;
            Bh[nt][1] = *(const unsigned*)(p + 16);
            Bl[nt][0] = *(const unsigned*)(p + GB_PLANE);
            Bl[nt][1] = *(const unsigned*)(p + GB_PLANE + 16);
        }
        #pragma unroll
        for (int mt = 0; mt < 2; mt++) {
            unsigned Ah[4], Al[4];
            ldmat4(Ah, bb + lmA + (uint32_t)(mt * 16 * 48));
            ldmat4(Al, bb + GA_PLANE + lmA + (uint32_t)(mt * 16 * 48));
            #pragma unroll
            for (int nt = 0; nt < 4; nt++) {
                mma16816(acc[mt][nt], Ah, Bh[nt]);
                mma16816(acc[mt][nt], Ah, Bl[nt]);
                mma16816(acc[mt][nt], Al, Bh[nt]);
            }
        }
        __syncthreads();
    }

    #pragma unroll
    for (int nt = 0; nt < 4; nt++) {
        int col = n0 + wn * 32 + nt * 8 + (lane & 3) * 2;
        float2 bv = *(const float2*)&bias[col];
        #pragma unroll
        for (int mt = 0; mt < 2; mt++) {
            int row = m0 + wm * 32 + mt * 16 + (lane >> 2);
            *(float2*)&g_gates[(size_t)row * G3H + col] =
                make_float2(acc[mt][nt][0] + bv.x, acc[mt][nt][1] + bv.y);
            *(float2*)&g_gates[(size_t)(row + 8) * G3H + col] =
                make_float2(acc[mt][nt][2] + bv.x, acc[mt][nt][3] + bv.y);
        }
    }
}

// ---------------------------------------------------------------------------
// Persistent GRU scan via mma.sync bf16 hi/lo — 32 warps (1024 threads).
// Warp (oct = w>>2: k-slice [oct*128,+128), mt = w&3: batches [mt*16,+16)).
// 8 k-tiles per warp; W hi/lo resident in smem; A staged warp-private
// (depth 2, hi+lo packed in 80B rows).  Red: 8 k-slices.
// ---------------------------------------------------------------------------
__global__ void __launch_bounds__(1024, 1)
gru_scan_mma(float* __restrict__ out,
             const float* __restrict__ w_hh,
             const float* __restrict__ b_hh)
{
    extern __shared__ __align__(16) char smem[];
    uint32_t sm32 = (uint32_t)__cvta_generic_to_shared((void*)smem);
    float* Red = (float*)(smem + OFF_RED);

    const int tid  = threadIdx.x;
    const int w    = tid >> 5;
    const int lane = tid & 31;
    const int oct  = w >> 2;              // k-slice index (0..7)
    const int mt   = w & 3;               // batch group (16 batches)
    const int j0   = blockIdx.x * JT;
    const int kofs = oct * 128;

    // ---- W -> smem bf16 hi/lo (once): rows 0..23 = g*8+jj ----
    for (int idx = tid; idx < NROW * (H_SZ / 4); idx += 1024) {
        int row = idx >> 8;
        int q   = idx & 255;
        int g = row >> 3, jj = row & 7;
        float4 v = *(const float4*)&w_hh[(size_t)(g * H_SZ + j0 + jj) * H_SZ + 4 * q];
        u16* hi = (u16*)(smem + (size_t)row * WROWB + (size_t)q * 8);
        u16* lo = (u16*)(smem + WPL + (size_t)row * WROWB + (size_t)q * 8);
        float vv[4] = {v.x, v.y, v.z, v.w};
        #pragma unroll
        for (int e = 0; e < 4; e++) {
            __nv_bfloat16 bh = __float2bfloat16_rn(vv[e]);
            hi[e] = __bfloat16_as_ushort(bh);
            lo[e] = __bfloat16_as_ushort(
                __float2bfloat16_rn(vv[e] - __bfloat162float(bh)));
        }
    }

    // ---- epilogue mapping: warps 0..15 own one output per thread ----
    const bool epi = (tid < 512);
    const int eb  = (tid >> 3) & 63;
    const int ejj = tid & 7;
    const int ej  = j0 + ejj;
    const float bhr = epi ? b_hh[ej] : 0.f;
    const float bhz = epi ? b_hh[H_SZ + ej] : 0.f;
    const float bhn = epi ? b_hh[2 * H_SZ + ej] : 0.f;

    // ---- A staging/ldmatrix mapping ----
    const uint32_t abase = sm32 + (uint32_t)(OFF_A + w * WARPA);
    const uint32_t lmA   = (uint32_t)((lane & 15) * AROW + (lane >> 4) * 16);
    const int srow  = lane >> 1;          // staging row handled twice (2 pieces)
    const int nl  = lane >> 2;            // n within tile for W frags
    const int klb = (lane & 3) * 4;       // k byte offset (2 bf16)

    __syncthreads();

    unsigned target = NBLK;
    float* hn_out = out + (size_t)T_LEN * B_SZ * H_SZ;
    float hpv = 0.f;

    #pragma unroll 1
    for (int t = 0; t < T_LEN; t++) {
        const u16* hhi = (t == 0) ? (const u16*)g_h0 : g_hhi;
        const u16* hlo = (t == 0) ? (const u16*)g_h0 : g_hlo;
        float* ho = out + (size_t)t * B_SZ * H_SZ;

        // x-gate prefetch (epilogue warps only; overlaps mainloop)
        float xr = 0.f, xz = 0.f, xn = 0.f;
        if (epi) {
            const float* xg = g_gates + (size_t)t * B_SZ * G3H
                            + (size_t)eb * G3H + ej;
            xr = __ldcg(&xg[0]);
            xz = __ldcg(&xg[H_SZ]);
            xn = __ldcg(&xg[2 * H_SZ]);
        }

        float acc[3][4];
        #pragma unroll
        for (int nt = 0; nt < 3; nt++)
            #pragma unroll
            for (int i = 0; i < 4; i++) acc[nt][i] = 0.f;

        // stage k-tile kt into buffer buf: 64 x 16B chunks, 2 per lane
        // chunk c: row = c>>2, piece = c&3 (0,1 = hi k-halves; 2,3 = lo)
        auto stageA = [&](int kt, int buf) {
            const int ktk = kofs + kt * 16;
            uint32_t bb = abase + (uint32_t)(buf * ATILE);
            #pragma unroll
            for (int i = 0; i < 2; i++) {
                int c = lane + 32 * i;
                int row   = c >> 2;
                int piece = c & 3;
                uint32_t dst = bb + (uint32_t)(row * AROW + piece * 16);
                const u16* src = ((piece & 2) ? hlo : hhi)
                               + (size_t)(mt * 16 + row) * H_SZ + ktk
                               + (piece & 1) * 8;
                CP16(dst, src);
            }
            CP_COMMIT();
        };

        stageA(0, 0);
        stageA(1, 1);

        #pragma unroll 1
        for (int kt = 0; kt < 8; kt++) {
            const int buf = kt & 1;
            CP_WAIT(1);
            __syncwarp();

            unsigned Ah[4], Al[4];
            uint32_t ab = abase + (uint32_t)(buf * ATILE) + lmA;
            ldmat4(Ah, ab);
            ldmat4(Al, ab + 32);

            const int kbyte = (kofs + kt * 16) * 2 + klb;
            #pragma unroll
            for (int nt = 0; nt < 3; nt++) {
                const char* pw = smem + (size_t)(nt * 8 + nl) * WROWB + kbyte;
                unsigned Bh[2], Bl[2];
                Bh[0] = *(const unsigned*)pw;
                Bh[1] = *(const unsigned*)(pw + 16);
                Bl[0] = *(const unsigned*)(pw + WPL);
                Bl[1] = *(const unsigned*)(pw + WPL + 16);
                mma16816(acc[nt], Ah, Bh);
                mma16816(acc[nt], Ah, Bl);
                mma16816(acc[nt], Al, Bh);
            }
            // stage the tile that reuses this buffer (reads already latched:
            // the HMMAs above consumed Ah/Al, so LDSM completed)
            if (kt < 6) stageA(kt + 2, buf);
            else        CP_COMMIT();
        }

        // ---- D frags -> Red[oct][batch][row24] ----
        {
            float* Rw = Red + (size_t)oct * 64 * REDW;
            const int br = lane >> 2;
            const int cl = (lane & 3) * 2;
            #pragma unroll
            for (int nt = 0; nt < 3; nt++) {
                *(float2*)&Rw[(mt * 16 + br) * REDW + nt * 8 + cl] =
                    make_float2(acc[nt][0], acc[nt][1]);
                *(float2*)&Rw[(mt * 16 + br + 8) * REDW + nt * 8 + cl] =
                    make_float2(acc[nt][2], acc[nt][3]);
            }
        }
        __syncthreads();

        // ---- fused gate epilogue (warps 0..15): 1 output per thread ----
        if (epi) {
            float sr = 0.f, sz = 0.f, sn = 0.f;
            #pragma unroll
            for (int s = 0; s < 8; s++) {
                const float* R = Red + ((size_t)s * 64 + eb) * REDW;
                sr += R[ejj];
                sz += R[8 + ejj];
                sn += R[16 + ejj];
            }
            float r = 1.f / (1.f + expf(-(xr + sr + bhr)));
            float z = 1.f / (1.f + expf(-(xz + sz + bhz)));
            float n = tanhf(xn + r * (sn + bhn));
            float hnew = (1.f - z) * n + z * hpv;
            hpv = hnew;
            size_t oidx = (size_t)eb * H_SZ + ej;
            __stcg(&ho[oidx], hnew);
            if (t == T_LEN - 1) __stcg(&hn_out[oidx], hnew);
            __nv_bfloat16 bhh = __float2bfloat16_rn(hnew);
            float fh = __bfloat162float(bhh);
            __nv_bfloat16 bll = __float2bfloat16_rn(hnew - fh);
            g_hhi[oidx] = __bfloat16_as_ushort(bhh);
            g_hlo[oidx] = __bfloat16_as_ushort(bll);
        }

        // ---- grid-wide sync ----
        __threadfence();
        __syncthreads();
        if (tid == 0) {
            asm volatile("red.release.gpu.global.add.u32 [%0], %1;"
                         :: "l"(&g_sync), "r"(1u) : "memory");
            unsigned vv;
            do {
                asm volatile("ld.acquire.gpu.global.u32 %0, [%1];"
                             : "=r"(vv) : "l"(&g_sync) : "memory");
            } while (vv < target);
        }
        __syncthreads();
        target += NBLK;
    }
}

extern "C" void kernel_launch(void* const* d_in, const int* in_sizes, int n_in,
                              void* d_out, int out_size)
{
    const float* x    = (const float*)d_in[0];   // (T, B, I)
    const float* w_ih = (const float*)d_in[1];   // (3H, I)
    const float* w_hh = (const float*)d_in[2];   // (3H, H)
    const float* b_ih = (const float*)d_in[3];   // (3H,)
    const float* b_hh = (const float*)d_in[4];   // (3H,)
    float* out = (float*)d_out;

    // reset the grid-sync counter (graph-capturable H2D memcpy)
    static unsigned h_zero = 0;
    void* sync_addr = nullptr;
    cudaGetSymbolAddress(&sync_addr, g_sync);
    cudaMemcpyAsync(sync_addr, &h_zero, sizeof(unsigned),
                    cudaMemcpyHostToDevice, 0);

    // Phase 0: convert x and w_ih to bf16 hi/lo
    u16 *xhi_p, *xlo_p, *whi_p, *wlo_p;
    cudaGetSymbolAddress((void**)&xhi_p, g_xhi);
    cudaGetSymbolAddress((void**)&xlo_p, g_xlo);
    cudaGetSymbolAddress((void**)&whi_p, g_whi);
    cudaGetSymbolAddress((void**)&wlo_p, g_wlo);
    {
        int n4x = M_TOT * I_SZ / 4;
        cvt_hilo<<<(n4x + 255) / 256, 256>>>(x, xhi_p, xlo_p, n4x);
        int n4w = G3H * I_SZ / 4;
        cvt_hilo<<<(n4w + 255) / 256, 256>>>(w_ih, whi_p, wlo_p, n4w);
    }

    // Phase 1: input projection GEMM (tensor cores)
    dim3 gridA(G3H / 64, M_TOT / 128);
    cudaFuncSetAttribute(gemm_xgates_mma,
                         cudaFuncAttributeMaxDynamicSharedMemorySize, SMEM_GEMM);
    gemm_xgates_mma<<<gridA, 256, SMEM_GEMM>>>(b_ih);

    // Phase 2: persistent tensor-core recurrent scan
    cudaFuncSetAttribute(gru_scan_mma,
                         cudaFuncAttributeMaxDynamicSharedMemorySize, SMEM_SCAN);
    gru_scan_mma<<<NBLK, 1024, SMEM_SCAN>>>(out, w_hh, b_hh);
}